// round 1
// baseline (speedup 1.0000x reference)
#include <cuda_runtime.h>
#include <cstdint>

// Problem constants
#define PASS_N   8
#define TRANS_N  8
#define NBINS    128
#define HIDDEN   256
#define NOUT     1024          // TRANS_N * NBINS
#define ROW_F    17            // floats per x row (and per out row)
#define TILE_M   32
#define NTHR     512
#define KC       16
#define NCHUNK   (HIDDEN / KC) // 16
#define HD_STRIDE (2 * TILE_M + 2)  // 66: duplicated h row pitch (pad kills bank conflicts)

// ---- shared memory layout (floats) ----
// h_dup : HIDDEN * HD_STRIDE                      (16896)
// W1_s  : PASS_N * HIDDEN                         ( 2048)
// xA_s  : TILE_M * PASS_N                         (  256)
// jf_s  : TILE_M * TRANS_N                        (  256)
// w_s   : 2 * KC * NOUT  (also reused as Q_s[TILE_M][NOUT])   (32768)
#define OFF_HDUP 0
#define OFF_W1   (OFF_HDUP + HIDDEN * HD_STRIDE)
#define OFF_XA   (OFF_W1 + PASS_N * HIDDEN)
#define OFF_JF   (OFF_XA + TILE_M * PASS_N)
#define OFF_WS   (((OFF_JF + TILE_M * TRANS_N) + 3) & ~3)   // 16B aligned
#define SMEM_FLOATS (OFF_WS + 2 * KC * NOUT)

__device__ __forceinline__ uint64_t fma2(uint64_t a, uint64_t b, uint64_t c) {
    uint64_t d;
    asm("fma.rn.f32x2 %0, %1, %2, %3;" : "=l"(d) : "l"(a), "l"(b), "l"(c));
    return d;
}
__device__ __forceinline__ void unpk(uint64_t v, float& lo, float& hi) {
    asm("mov.b64 {%0, %1}, %2;" : "=f"(lo), "=f"(hi) : "l"(v));
}
__device__ __forceinline__ void cp16(float* smem_dst, const float* gsrc) {
    uint32_t s = (uint32_t)__cvta_generic_to_shared(smem_dst);
    asm volatile("cp.async.cg.shared.global [%0], [%1], 16;" :: "r"(s), "l"(gsrc));
}
__device__ __forceinline__ void cp_commit() { asm volatile("cp.async.commit_group;"); }
template <int N> __device__ __forceinline__ void cp_wait() {
    asm volatile("cp.async.wait_group %0;" :: "n"(N));
}

__global__ __launch_bounds__(NTHR, 1)
void gplc_kernel(const float* __restrict__ x,
                 const float* __restrict__ W1,
                 const float* __restrict__ b1,
                 const float* __restrict__ W2,
                 const float* __restrict__ b2,
                 float* __restrict__ out)
{
    extern __shared__ float sm[];
    float* h_dup = sm + OFF_HDUP;
    float* W1_s  = sm + OFF_W1;
    float* xA_s  = sm + OFF_XA;
    float* jf_s  = sm + OFF_JF;
    float* w_s   = sm + OFF_WS;      // 2 x [KC][NOUT]
    float* Q_s   = w_s;              // reused post-GEMM: [TILE_M][NOUT]

    const int tid = threadIdx.x;
    const int g0  = blockIdx.x * TILE_M;

    // ---- prefetch W2 chunk 0 into buffer 0 (overlaps with h computation) ----
    {
        const float* src = W2;
        float* dst = w_s;
        #pragma unroll
        for (int u = tid; u < KC * NOUT / 4; u += NTHR) cp16(dst + 4 * u, src + 4 * u);
        cp_commit();
    }

    // ---- stage W1 and xA ----
    for (int i = tid; i < PASS_N * HIDDEN; i += NTHR) W1_s[i] = W1[i];
    if (tid < TILE_M * PASS_N) {
        int m = tid >> 3, k = tid & 7;
        xA_s[tid] = x[(size_t)(g0 + m) * ROW_F + k];
    }
    __syncthreads();

    // ---- h = relu(xA @ W1 + b1), stored transposed + duplicated: h_dup[j][2m]=h_dup[j][2m+1]=h[m][j]
    {
        const int j  = tid & (HIDDEN - 1);
        const int mb = (tid >> 8) * (TILE_M / 2);   // 0 or 16
        float w1r[PASS_N];
        #pragma unroll
        for (int k = 0; k < PASS_N; k++) w1r[k] = W1_s[k * HIDDEN + j];
        const float bj = b1[j];
        #pragma unroll
        for (int mi = 0; mi < TILE_M / 2; mi++) {
            const int m = mb + mi;
            float acc = bj;
            #pragma unroll
            for (int k = 0; k < PASS_N; k++) acc = fmaf(xA_s[m * PASS_N + k], w1r[k], acc);
            acc = fmaxf(acc, 0.0f);
            float* p = &h_dup[j * HD_STRIDE + 2 * m];
            p[0] = acc; p[1] = acc;
        }
    }

    // ---- GEMM: logits[32][1024] = h @ W2, f32x2-packed column pairs ----
    const int c_t = tid & 127;       // 128 column-thread groups
    const int r_g = tid >> 7;        // 4 row groups x 8 rows
    uint64_t acc[8][4];
    #pragma unroll
    for (int r = 0; r < 8; r++)
        #pragma unroll
        for (int i = 0; i < 4; i++) acc[r][i] = 0ULL;

    for (int c = 0; c < NCHUNK; c++) {
        if (c + 1 < NCHUNK) {  // prefetch next chunk into other buffer
            const float* src = W2 + (size_t)(c + 1) * KC * NOUT;
            float* dst = w_s + ((c + 1) & 1) * KC * NOUT;
            #pragma unroll
            for (int u = tid; u < KC * NOUT / 4; u += NTHR) cp16(dst + 4 * u, src + 4 * u);
            cp_commit();
            cp_wait<1>();
        } else {
            cp_wait<0>();
        }
        __syncthreads();   // chunk c visible to all; prior compute done before refill

        const float* wb = w_s + (c & 1) * KC * NOUT;
        #pragma unroll
        for (int k = 0; k < KC; k++) {
            const int j = c * KC + k;
            uint64_t wv[4];
            #pragma unroll
            for (int i = 0; i < 4; i++)
                wv[i] = *(const uint64_t*)&wb[k * NOUT + 2 * (c_t + 128 * i)];
            #pragma unroll
            for (int r = 0; r < 8; r++) {
                const uint64_t hv = *(const uint64_t*)&h_dup[j * HD_STRIDE + 2 * (r_g * 8 + r)];
                #pragma unroll
                for (int i = 0; i < 4; i++) acc[r][i] = fma2(hv, wv[i], acc[r][i]);
            }
        }
        __syncthreads();   // all reads of this buffer done before it is refilled
    }

    // ---- epilogue: +b2, exp, store Q tile to smem (reusing w_s) ----
    {
        float2 b2v[4];
        #pragma unroll
        for (int i = 0; i < 4; i++)
            b2v[i] = *(const float2*)&b2[2 * (c_t + 128 * i)];
        #pragma unroll
        for (int r = 0; r < 8; r++) {
            const int m = r_g * 8 + r;
            #pragma unroll
            for (int i = 0; i < 4; i++) {
                const int col = 2 * (c_t + 128 * i);
                float lo, hi; unpk(acc[r][i], lo, hi);
                lo = __expf(lo + b2v[i].x);
                hi = __expf(hi + b2v[i].y);
                *(float2*)&Q_s[m * NOUT + col] = make_float2(lo, hi);
            }
        }
    }
    __syncthreads();

    // ---- per-(row, transform) 128-bin scan + gather: one warp per task ----
    {
        const int warp = tid >> 5, lane = tid & 31;
        #pragma unroll 1
        for (int it = 0; it < 16; it++) {
            const int task = warp * 16 + it;           // 256 tasks = 32 rows x 8 transforms
            const int m = task >> 3, t = task & 7;
            const float4 v = *(const float4*)&Q_s[m * NOUT + t * NBINS + lane * 4];
            const float s = v.x + v.y + v.z + v.w;
            float incl = s;
            #pragma unroll
            for (int o = 1; o < 32; o <<= 1) {
                float n = __shfl_up_sync(0xffffffffu, incl, o);
                if (lane >= o) incl += n;
            }
            const float total = __shfl_sync(0xffffffffu, incl, 31);
            const float excl  = incl - s;

            const float xb   = x[(size_t)(g0 + m) * ROW_F + PASS_N + t];
            const float a    = xb * (float)NBINS;
            const float bf   = floorf(a);
            const int   bin  = min(max((int)bf, 0), NBINS - 1);
            const float frac = a - bf;
            const int lane_b = bin >> 2, jj = bin & 3;

            float pre = excl;
            if (jj > 0) pre += v.x;
            if (jj > 1) pre += v.y;
            if (jj > 2) pre += v.z;
            float qb = (jj == 0) ? v.x : (jj == 1) ? v.y : (jj == 2) ? v.z : v.w;
            pre = __shfl_sync(0xffffffffu, pre, lane_b);
            qb  = __shfl_sync(0xffffffffu, qb,  lane_b);

            if (lane == 0) {
                const float inv = 1.0f / total;
                out[(size_t)(g0 + m) * ROW_F + PASS_N + t] = (qb * frac + pre) * inv;
                jf_s[m * TRANS_N + t] = qb * (float)NBINS * inv;
            }
        }
    }
    __syncthreads();

    // ---- jacobian + pass-through copy ----
    if (tid < TILE_M) {
        const int m = tid;
        float jac = x[(size_t)(g0 + m) * ROW_F + 16];
        #pragma unroll
        for (int t = 0; t < TRANS_N; t++) jac *= jf_s[m * TRANS_N + t];
        out[(size_t)(g0 + m) * ROW_F + 16] = jac;
    }
    if (tid < TILE_M * PASS_N) {
        const int m = tid >> 3, k = tid & 7;
        out[(size_t)(g0 + m) * ROW_F + k] = xA_s[tid];
    }
}

extern "C" void kernel_launch(void* const* d_in, const int* in_sizes, int n_in,
                              void* d_out, int out_size) {
    const float* x  = (const float*)d_in[0];
    const float* W1 = (const float*)d_in[1];
    const float* b1 = (const float*)d_in[2];
    const float* W2 = (const float*)d_in[3];
    const float* b2 = (const float*)d_in[4];
    float* out = (float*)d_out;

    const int B = in_sizes[0] / ROW_F;          // 131072
    const int smem_bytes = SMEM_FLOATS * 4;     // ~204 KB

    cudaFuncSetAttribute(gplc_kernel, cudaFuncAttributeMaxDynamicSharedMemorySize, smem_bytes);
    gplc_kernel<<<B / TILE_M, NTHR, smem_bytes>>>(x, W1, b1, W2, b2, out);
}

// round 4
// speedup vs baseline: 2.5021x; 2.5021x over previous
#include <cuda_runtime.h>
#include <cuda_bf16.h>
#include <cstdint>

#define NBINS   128
#define HIDDEN  256
#define ROW_F   17
#define TILE_M  128
#define NTHR    256

// ---- smem float offsets ----
#define OFF_B2   0                 // 1024 f
#define OFF_BIN  1024              // u8[128][8] = 256 f
#define OFF_E    1280              // 2560 f: prologue W1T(2048)+b1(256); epilogue segsums[128][20]
#define OFF_QAT  3840              // 128 f
#define OFF_PRE  3968              // 128 f
#define OFF_A    4096              // byte 16384: A hi(4 panels x 16KB) + lo = 128KB
#define OFF_BST  36864             // byte 147456: 2 stages x 32KB
#define SMEM_FLOATS (OFF_BST + 16384)   // 53248 f = 208KB

// B fragments, exact mma.m16n8k16 B-operand order, hi+lo packed per lane:
// [nc(8)][ks(4)][k16(4)][n8(16)][lane(32)] -> uint4{bh0, bh1, bl0, bl1}
__device__ uint4 g_bfrag[8 * 4 * 4 * 16 * 32];   // 1 MB

// ---------------- helpers ----------------
__device__ __forceinline__ uint32_t smem_u32(const void* p) {
    uint32_t a;
    asm("{ .reg .u64 t; cvta.to.shared.u64 t, %1; cvt.u32.u64 %0, t; }" : "=r"(a) : "l"(p));
    return a;
}
__device__ __forceinline__ uint32_t packbf(float lo, float hi) {
    __nv_bfloat162 t = __floats2bfloat162_rn(lo, hi);   // x = lo (low 16 bits)
    return *(uint32_t*)&t;
}
__device__ __forceinline__ void ldm4(uint32_t* r, uint32_t addr) {
    asm volatile("ldmatrix.sync.aligned.m8n8.x4.shared.b16 {%0,%1,%2,%3}, [%4];"
        : "=r"(r[0]), "=r"(r[1]), "=r"(r[2]), "=r"(r[3]) : "r"(addr));
}
__device__ __forceinline__ void mma_bf16(float* d, const uint32_t* a, uint32_t b0, uint32_t b1) {
    asm volatile("mma.sync.aligned.m16n8k16.row.col.f32.bf16.bf16.f32 "
        "{%0,%1,%2,%3}, {%4,%5,%6,%7}, {%8,%9}, {%0,%1,%2,%3};"
        : "+f"(d[0]), "+f"(d[1]), "+f"(d[2]), "+f"(d[3])
        : "r"(a[0]), "r"(a[1]), "r"(a[2]), "r"(a[3]), "r"(b0), "r"(b1));
}
__device__ __forceinline__ void cp16(uint32_t sdst, const void* gsrc) {
    asm volatile("cp.async.cg.shared.global [%0], [%1], 16;" :: "r"(sdst), "l"(gsrc));
}
#define CP_COMMIT() asm volatile("cp.async.commit_group;")
#define CP_WAIT(n)  asm volatile("cp.async.wait_group %0;" :: "n"(n))

// ---------------- prep: W2 -> split bf16 fragments ----------------
__global__ void gplc_prep(const float* __restrict__ W2) {
    const int idx  = blockIdx.x * 256 + threadIdx.x;       // 0..65535
    const int lane = idx & 31;
    const int n8   = (idx >> 5) & 15;
    const int k16  = (idx >> 9) & 3;
    const int ks   = (idx >> 11) & 3;
    const int nc   = idx >> 13;
    const int n  = nc * 128 + n8 * 8 + (lane >> 2);
    const int k0 = ks * 64 + k16 * 16 + 2 * (lane & 3);
    const float v0 = W2[(size_t)k0 * 1024 + n];
    const float v1 = W2[(size_t)(k0 + 1) * 1024 + n];
    const float v8 = W2[(size_t)(k0 + 8) * 1024 + n];
    const float v9 = W2[(size_t)(k0 + 9) * 1024 + n];
    const uint32_t h0 = packbf(v0, v1), h1 = packbf(v8, v9);
    const float e0 = v0 - __uint_as_float(h0 << 16);
    const float e1 = v1 - __uint_as_float(h0 & 0xffff0000u);
    const float e8 = v8 - __uint_as_float(h1 << 16);
    const float e9 = v9 - __uint_as_float(h1 & 0xffff0000u);
    g_bfrag[idx] = make_uint4(h0, h1, packbf(e0, e1), packbf(e8, e9));
}

// ---------------- main ----------------
__global__ __launch_bounds__(NTHR, 1)
void gplc_main(const float* __restrict__ x,
               const float* __restrict__ W1,
               const float* __restrict__ b1,
               const float* __restrict__ b2,
               float* __restrict__ out)
{
    extern __shared__ float sm[];
    const uint32_t smem_base = smem_u32(sm);
    const int tid  = threadIdx.x;
    const int w    = tid >> 5, lane = tid & 31;
    const int wm   = w >> 1, wn = w & 1;            // warp grid 4m x 2n
    const int m0   = wm * 32;                       // warp rows m0..m0+31
    const int l4   = lane & 3, lq = lane >> 2;
    const int g0   = blockIdx.x * TILE_M;

    // ---- prologue staging ----
    for (int i = tid; i < HIDDEN * 8; i += NTHR) {   // W1 transposed [k][8]  (FIXED bound)
        int k = i >> 3, p = i & 7;
        sm[OFF_E + i] = W1[p * HIDDEN + k];
    }
    for (int i = tid; i < HIDDEN; i += NTHR) sm[OFF_E + 2048 + i] = b1[i];
    for (int i = tid; i < 1024; i += NTHR) sm[OFF_B2 + i] = b2[i];
    for (int i = tid; i < TILE_M * 8; i += NTHR) {  // bins u8
        int m = i >> 3, t = i & 7;
        float xb = __ldg(&x[(size_t)(g0 + m) * ROW_F + 8 + t]);
        int b = (int)floorf(xb * (float)NBINS);
        ((uint8_t*)&sm[OFF_BIN])[i] = (uint8_t)min(max(b, 0), NBINS - 1);
    }
    // prefetch B stage 0
    {
        const char* src = (const char*)g_bfrag;
        const uint32_t dst = smem_base + OFF_BST * 4;
        #pragma unroll
        for (int j = 0; j < 8; j++) {
            int off = (tid + j * NTHR) * 16;
            cp16(dst + off, src + off);
        }
        CP_COMMIT();
    }
    __syncthreads();

    // ---- first layer: h = relu(xA@W1+b1), split bf16, store to swizzled A panels ----
    {
        const int m = tid & 127, half = tid >> 7;   // half: k in [half*128, half*128+128)
        float xr[8];
        #pragma unroll
        for (int p = 0; p < 8; p++) xr[p] = __ldg(&x[(size_t)(g0 + m) * ROW_F + p]);
        const float4* W4 = (const float4*)&sm[OFF_E];
        char* Ahi = (char*)sm + OFF_A * 4;
        char* Alo = Ahi + 65536;
        #pragma unroll
        for (int c = 0; c < 64; c++) {
            const int k = half * 128 + 2 * c;
            float4 wa = W4[k * 2], wb = W4[k * 2 + 1], wc = W4[k * 2 + 2], wd = W4[k * 2 + 3];
            float a0 = sm[OFF_E + 2048 + k], a1 = sm[OFF_E + 2048 + k + 1];
            a0 = fmaf(xr[0], wa.x, a0); a0 = fmaf(xr[1], wa.y, a0);
            a0 = fmaf(xr[2], wa.z, a0); a0 = fmaf(xr[3], wa.w, a0);
            a0 = fmaf(xr[4], wb.x, a0); a0 = fmaf(xr[5], wb.y, a0);
            a0 = fmaf(xr[6], wb.z, a0); a0 = fmaf(xr[7], wb.w, a0);
            a1 = fmaf(xr[0], wc.x, a1); a1 = fmaf(xr[1], wc.y, a1);
            a1 = fmaf(xr[2], wc.z, a1); a1 = fmaf(xr[3], wc.w, a1);
            a1 = fmaf(xr[4], wd.x, a1); a1 = fmaf(xr[5], wd.y, a1);
            a1 = fmaf(xr[6], wd.z, a1); a1 = fmaf(xr[7], wd.w, a1);
            a0 = fmaxf(a0, 0.0f); a1 = fmaxf(a1, 0.0f);
            uint32_t hp = packbf(a0, a1);
            float f0 = __uint_as_float(hp << 16);
            float f1 = __uint_as_float(hp & 0xffff0000u);
            uint32_t lp = packbf(a0 - f0, a1 - f1);
            const int panel = k >> 6, kin = k & 63;
            const uint32_t off = (uint32_t)panel * 16384 + (uint32_t)(m << 7)
                               + ((((uint32_t)(kin >> 3)) ^ (uint32_t)(m & 7)) << 4)
                               + (uint32_t)((kin & 7) << 1);
            *(uint32_t*)(Ahi + off) = hp;
            *(uint32_t*)(Alo + off) = lp;
        }
    }

    // per-lane A-row constants
    const int lr = lane & 15, hb = lane >> 4;
    const int rowA0 = m0 + lr, rowA1 = m0 + 16 + lr;
    const uint32_t rb0 = (uint32_t)rowA0 << 7, rb1 = (uint32_t)rowA1 << 7;
    const uint32_t rx0 = rowA0 & 7, rx1 = rowA1 & 7;
    // epilogue row ids
    const int R0 = m0 + lq, R1 = m0 + lq + 8, R2 = m0 + 16 + lq, R3 = m0 + 24 + lq;

    float jac = (tid < TILE_M) ? __ldg(&x[(size_t)(g0 + tid) * ROW_F + 16]) : 0.0f;

    float acc[2][8][4];

    for (int s = 0; s < 32; s++) {
        const int nc = s >> 2, ks = s & 3;

        __syncthreads();   // prev reads of buf (s+1)&1 done; E-region reuse safe
        if (s + 1 < 32) {  // prefetch next stage
            const char* src = (const char*)g_bfrag + (size_t)(s + 1) * 32768;
            const uint32_t dst = smem_base + OFF_BST * 4 + ((s + 1) & 1) * 32768;
            #pragma unroll
            for (int j = 0; j < 8; j++) {
                int off = (tid + j * NTHR) * 16;
                cp16(dst + off, src + off);
            }
        }
        CP_COMMIT();
        CP_WAIT(1);
        __syncthreads();   // stage s visible to all

        if (ks == 0) {
            #pragma unroll
            for (int mt = 0; mt < 2; mt++)
                #pragma unroll
                for (int nt = 0; nt < 8; nt++)
                    #pragma unroll
                    for (int i = 0; i < 4; i++) acc[mt][nt][i] = 0.0f;
        }

        const uint32_t aHi = smem_base + OFF_A * 4 + (uint32_t)ks * 16384;
        const uint32_t aLo = aHi + 65536;
        const int bbase = OFF_BST + (s & 1) * 8192;

        #pragma unroll
        for (int k16 = 0; k16 < 4; k16++) {
            const uint32_t ch = (uint32_t)(k16 * 2 + hb);
            uint32_t ah0[4], ah1[4], al0[4], al1[4];
            ldm4(ah0, aHi + rb0 + ((ch ^ rx0) << 4));
            ldm4(ah1, aHi + rb1 + ((ch ^ rx1) << 4));
            ldm4(al0, aLo + rb0 + ((ch ^ rx0) << 4));
            ldm4(al1, aLo + rb1 + ((ch ^ rx1) << 4));
            #pragma unroll
            for (int nt = 0; nt < 8; nt++) {
                const int fo = bbase + ((k16 * 16 + wn * 8 + nt) * 32 + lane) * 4;
                uint4 bv = *(const uint4*)&sm[fo];
                mma_bf16(acc[0][nt], ah0, bv.x, bv.y);   // hi*hi
                mma_bf16(acc[1][nt], ah1, bv.x, bv.y);
                mma_bf16(acc[0][nt], ah0, bv.z, bv.w);   // hi*lo
                mma_bf16(acc[1][nt], ah1, bv.z, bv.w);
                mma_bf16(acc[0][nt], al0, bv.x, bv.y);   // lo*hi
                mma_bf16(acc[1][nt], al1, bv.x, bv.y);
            }
        }

        if (ks == 3) {
            // ---- epilogue for transform nc ----
            const uint8_t* binp = (const uint8_t*)&sm[OFF_BIN];
            const int b_r[4] = { binp[R0 * 8 + nc], binp[R1 * 8 + nc],
                                 binp[R2 * 8 + nc], binp[R3 * 8 + nc] };
            #pragma unroll
            for (int mt = 0; mt < 2; mt++) {
                const int Ra = mt ? R2 : R0;
                const int Rb = mt ? R3 : R1;
                const int ba = b_r[mt * 2 + 0], bb = b_r[mt * 2 + 1];
                #pragma unroll
                for (int nt = 0; nt < 8; nt++) {
                    const int seg = wn * 8 + nt;
                    const int n = nc * 128 + seg * 8 + 2 * l4;
                    const float2 b2v = *(const float2*)&sm[OFF_B2 + n];
                    float q0 = __expf(acc[mt][nt][0] + b2v.x);
                    float q1 = __expf(acc[mt][nt][1] + b2v.y);
                    float q2 = __expf(acc[mt][nt][2] + b2v.x);
                    float q3 = __expf(acc[mt][nt][3] + b2v.y);
                    float p0 = q0 + q1, p1 = q2 + q3;
                    // inclusive quad prefix
                    float ip0 = p0, ip1 = p1, u;
                    u = __shfl_up_sync(0xffffffffu, ip0, 1); if (l4 >= 1) ip0 += u;
                    u = __shfl_up_sync(0xffffffffu, ip0, 2); if (l4 >= 2) ip0 += u;
                    u = __shfl_up_sync(0xffffffffu, ip1, 1); if (l4 >= 1) ip1 += u;
                    u = __shfl_up_sync(0xffffffffu, ip1, 2); if (l4 >= 2) ip1 += u;
                    const float s0 = __shfl_sync(0xffffffffu, ip0, lane | 3);
                    const float s1 = __shfl_sync(0xffffffffu, ip1, lane | 3);
                    if (l4 == 0) {
                        sm[OFF_E + Ra * 20 + seg] = s0;
                        sm[OFF_E + Rb * 20 + seg] = s1;
                    }
                    if ((ba >> 3) == seg && l4 == ((ba & 7) >> 1)) {
                        sm[OFF_PRE + Ra] = (ip0 - p0) + ((ba & 1) ? q0 : 0.0f);
                        sm[OFF_QAT + Ra] = (ba & 1) ? q1 : q0;
                    }
                    if ((bb >> 3) == seg && l4 == ((bb & 7) >> 1)) {
                        sm[OFF_PRE + Rb] = (ip1 - p1) + ((bb & 1) ? q2 : 0.0f);
                        sm[OFF_QAT + Rb] = (bb & 1) ? q3 : q2;
                    }
                }
            }
            __syncthreads();

            if (tid < TILE_M) {
                const int row = tid;
                const int b = ((const uint8_t*)&sm[OFF_BIN])[row * 8 + nc];
                const int bs = b >> 3;
                float tot = 0.0f, pref = 0.0f;
                #pragma unroll
                for (int sg = 0; sg < 16; sg++) {
                    float v = sm[OFF_E + row * 20 + sg];
                    tot += v;
                    if (sg < bs) pref += v;
                }
                pref += sm[OFF_PRE + row];
                const float qat = sm[OFF_QAT + row];
                const float xb = __ldg(&x[(size_t)(g0 + row) * ROW_F + 8 + nc]);
                const float aa = xb * (float)NBINS;
                const float frac = aa - floorf(aa);
                const float inv = 1.0f / tot;
                out[(size_t)(g0 + row) * ROW_F + 8 + nc] = (qat * frac + pref) * inv;
                jac *= qat * (float)NBINS * inv;
            }
        }
    }

    // ---- jacobian + pass-through ----
    if (tid < TILE_M)
        out[(size_t)(g0 + tid) * ROW_F + 16] = jac;
    for (int i = tid; i < TILE_M * 8; i += NTHR) {
        int m = i >> 3, p = i & 7;
        out[(size_t)(g0 + m) * ROW_F + p] = __ldg(&x[(size_t)(g0 + m) * ROW_F + p]);
    }
}

extern "C" void kernel_launch(void* const* d_in, const int* in_sizes, int n_in,
                              void* d_out, int out_size) {
    const float* x  = (const float*)d_in[0];
    const float* W1 = (const float*)d_in[1];
    const float* b1 = (const float*)d_in[2];
    const float* W2 = (const float*)d_in[3];
    const float* b2 = (const float*)d_in[4];
    float* out = (float*)d_out;

    const int B = in_sizes[0] / ROW_F;          // 131072
    const int smem_bytes = SMEM_FLOATS * 4;     // 208 KB

    gplc_prep<<<256, 256>>>(W2);

    cudaFuncSetAttribute(gplc_main, cudaFuncAttributeMaxDynamicSharedMemorySize, smem_bytes);
    gplc_main<<<B / TILE_M, NTHR, smem_bytes>>>(x, W1, b1, b2, out);
}

// round 5
// speedup vs baseline: 4.8791x; 1.9500x over previous
#include <cuda_runtime.h>
#include <cuda_fp16.h>
#include <cstdint>

#define NBINS   128
#define HIDDEN  256
#define ROW_F   17
#define TILE_M  128
#define NTHR    512

// ---- smem float offsets ----
#define OFF_B2   0                 // 1024 f
#define OFF_BIN  1024              // u8[128][8] = 256 f
#define OFF_E    1280              // 2560 f: prologue W1T(2048)+b1(256); epilogue segsums[128][20]
#define OFF_QAT  3840              // 128 f
#define OFF_PRE  3968              // 128 f
#define OFF_A    4096              // byte 16384: A fp16, 4 panels x 16KB = 64KB
#define OFF_BST  20480             // byte 81920: 4 slots x 16KB = 64KB
#define SMEM_FLOATS (OFF_BST + 16384)   // 36864 f = 144KB

// B fragments, mma.m16n8k16 B-operand order, fp16:
// [nc(8)][ks(4)][k16(4)][n8(16)][lane(32)] -> uint2{b0, b1}
__device__ uint2 g_bfrag[8 * 4 * 4 * 16 * 32];   // 512 KB

// ---------------- helpers ----------------
__device__ __forceinline__ uint32_t smem_u32(const void* p) {
    uint32_t a;
    asm("{ .reg .u64 t; cvta.to.shared.u64 t, %1; cvt.u32.u64 %0, t; }" : "=r"(a) : "l"(p));
    return a;
}
__device__ __forceinline__ uint32_t packh2(float lo, float hi) {
    __half2 t = __floats2half2_rn(lo, hi);   // x = lo (low 16 bits)
    return *(uint32_t*)&t;
}
__device__ __forceinline__ void ldm4(uint32_t* r, uint32_t addr) {
    asm volatile("ldmatrix.sync.aligned.m8n8.x4.shared.b16 {%0,%1,%2,%3}, [%4];"
        : "=r"(r[0]), "=r"(r[1]), "=r"(r[2]), "=r"(r[3]) : "r"(addr));
}
__device__ __forceinline__ void mma_fp16(float* d, const uint32_t* a, uint32_t b0, uint32_t b1) {
    asm volatile("mma.sync.aligned.m16n8k16.row.col.f32.f16.f16.f32 "
        "{%0,%1,%2,%3}, {%4,%5,%6,%7}, {%8,%9}, {%0,%1,%2,%3};"
        : "+f"(d[0]), "+f"(d[1]), "+f"(d[2]), "+f"(d[3])
        : "r"(a[0]), "r"(a[1]), "r"(a[2]), "r"(a[3]), "r"(b0), "r"(b1));
}
__device__ __forceinline__ void cp16(uint32_t sdst, const void* gsrc) {
    asm volatile("cp.async.cg.shared.global [%0], [%1], 16;" :: "r"(sdst), "l"(gsrc));
}
#define CP_COMMIT() asm volatile("cp.async.commit_group;")
#define CP_WAIT(n)  asm volatile("cp.async.wait_group %0;" :: "n"(n))

// ---------------- prep: W2 -> fp16 fragments ----------------
__global__ void gplc_prep(const float* __restrict__ W2) {
    const int idx  = blockIdx.x * 256 + threadIdx.x;       // 0..65535
    const int lane = idx & 31;
    const int n8   = (idx >> 5) & 15;
    const int k16  = (idx >> 9) & 3;
    const int ks   = (idx >> 11) & 3;
    const int nc   = idx >> 13;
    const int n  = nc * 128 + n8 * 8 + (lane >> 2);
    const int k0 = ks * 64 + k16 * 16 + 2 * (lane & 3);
    const float v0 = W2[(size_t)k0 * 1024 + n];
    const float v1 = W2[(size_t)(k0 + 1) * 1024 + n];
    const float v8 = W2[(size_t)(k0 + 8) * 1024 + n];
    const float v9 = W2[(size_t)(k0 + 9) * 1024 + n];
    g_bfrag[idx] = make_uint2(packh2(v0, v1), packh2(v8, v9));
}

// ---------------- main ----------------
__global__ __launch_bounds__(NTHR, 1)
void gplc_main(const float* __restrict__ x,
               const float* __restrict__ W1,
               const float* __restrict__ b1,
               const float* __restrict__ b2,
               float* __restrict__ out)
{
    extern __shared__ float sm[];
    const uint32_t smem_base = smem_u32(sm);
    const int tid  = threadIdx.x;
    const int w    = tid >> 5, lane = tid & 31;
    const int wm   = w >> 2, wn = w & 3;            // warp grid 4m x 4n
    const int m0   = wm * 32;                       // warp rows m0..m0+31
    const int l4   = lane & 3, lq = lane >> 2;
    const int g0   = blockIdx.x * TILE_M;

    // prefetch B stages 0..2 (3 groups)
    #pragma unroll
    for (int st = 0; st < 3; st++) {
        const char* src = (const char*)g_bfrag + (size_t)st * 16384;
        const uint32_t dst = smem_base + OFF_BST * 4 + st * 16384;
        #pragma unroll
        for (int j = 0; j < 2; j++) {
            int off = (tid + j * NTHR) * 16;
            cp16(dst + off, src + off);
        }
        CP_COMMIT();
    }

    // ---- prologue staging ----
    for (int i = tid; i < HIDDEN * 8; i += NTHR) {   // W1 transposed [k][8]
        int k = i >> 3, p = i & 7;
        sm[OFF_E + i] = W1[p * HIDDEN + k];
    }
    for (int i = tid; i < HIDDEN; i += NTHR) sm[OFF_E + 2048 + i] = b1[i];
    for (int i = tid; i < 1024; i += NTHR) sm[OFF_B2 + i] = b2[i];
    for (int i = tid; i < TILE_M * 8; i += NTHR) {   // bins u8
        int m = i >> 3, t = i & 7;
        float xb = __ldg(&x[(size_t)(g0 + m) * ROW_F + 8 + t]);
        int b = (int)floorf(xb * (float)NBINS);
        ((uint8_t*)&sm[OFF_BIN])[i] = (uint8_t)min(max(b, 0), NBINS - 1);
    }
    __syncthreads();

    // ---- first layer: h = relu(xA@W1+b1) -> fp16, swizzled A panels ----
    {
        const int m = tid & 127, quarter = tid >> 7;   // k in [quarter*64, +64)
        float xr[8];
        #pragma unroll
        for (int p = 0; p < 8; p++) xr[p] = __ldg(&x[(size_t)(g0 + m) * ROW_F + p]);
        const float4* W4 = (const float4*)&sm[OFF_E];
        char* Ap = (char*)sm + OFF_A * 4 + quarter * 16384;
        #pragma unroll
        for (int c = 0; c < 32; c++) {
            const int kin = 2 * c;
            const int k = quarter * 64 + kin;
            float4 wa = W4[k * 2], wb = W4[k * 2 + 1], wc = W4[k * 2 + 2], wd = W4[k * 2 + 3];
            float a0 = sm[OFF_E + 2048 + k], a1 = sm[OFF_E + 2048 + k + 1];
            a0 = fmaf(xr[0], wa.x, a0); a0 = fmaf(xr[1], wa.y, a0);
            a0 = fmaf(xr[2], wa.z, a0); a0 = fmaf(xr[3], wa.w, a0);
            a0 = fmaf(xr[4], wb.x, a0); a0 = fmaf(xr[5], wb.y, a0);
            a0 = fmaf(xr[6], wb.z, a0); a0 = fmaf(xr[7], wb.w, a0);
            a1 = fmaf(xr[0], wc.x, a1); a1 = fmaf(xr[1], wc.y, a1);
            a1 = fmaf(xr[2], wc.z, a1); a1 = fmaf(xr[3], wc.w, a1);
            a1 = fmaf(xr[4], wd.x, a1); a1 = fmaf(xr[5], wd.y, a1);
            a1 = fmaf(xr[6], wd.z, a1); a1 = fmaf(xr[7], wd.w, a1);
            a0 = fmaxf(a0, 0.0f); a1 = fmaxf(a1, 0.0f);
            const uint32_t off = (uint32_t)(m << 7)
                               + ((((uint32_t)(kin >> 3)) ^ (uint32_t)(m & 7)) << 4)
                               + (uint32_t)((kin & 7) << 1);
            *(uint32_t*)(Ap + off) = packh2(a0, a1);
        }
    }

    // per-lane A-row constants (ldmatrix addressing)
    const int lr = lane & 15, hb = lane >> 4;
    const int rowA0 = m0 + lr, rowA1 = m0 + 16 + lr;
    const uint32_t rb0 = (uint32_t)rowA0 << 7, rb1 = (uint32_t)rowA1 << 7;
    const uint32_t rx0 = rowA0 & 7, rx1 = rowA1 & 7;
    // epilogue row ids
    const int R0 = m0 + lq, R1 = m0 + lq + 8, R2 = m0 + 16 + lq, R3 = m0 + 24 + lq;

    float jac = (tid < TILE_M) ? __ldg(&x[(size_t)(g0 + tid) * ROW_F + 16]) : 0.0f;

    float acc[2][4][4];

    for (int s = 0; s < 32; s++) {
        const int nc = s >> 2, ks = s & 3;

        CP_WAIT(2);          // own cp groups: stage s complete
        __syncthreads();     // publish stage s; all warps done reading stage s-1

        if (s + 3 < 32) {    // refill slot (s+3)&3 == (s-1)&3
            const char* src = (const char*)g_bfrag + (size_t)(s + 3) * 16384;
            const uint32_t dst = smem_base + OFF_BST * 4 + ((s + 3) & 3) * 16384;
            #pragma unroll
            for (int j = 0; j < 2; j++) {
                int off = (tid + j * NTHR) * 16;
                cp16(dst + off, src + off);
            }
        }
        CP_COMMIT();

        if (ks == 0) {
            #pragma unroll
            for (int mt = 0; mt < 2; mt++)
                #pragma unroll
                for (int nt = 0; nt < 4; nt++)
                    #pragma unroll
                    for (int i = 0; i < 4; i++) acc[mt][nt][i] = 0.0f;
        }

        const uint32_t aP = smem_base + OFF_A * 4 + (uint32_t)ks * 16384;
        const int bbase = OFF_BST + (s & 3) * 4096;

        #pragma unroll
        for (int k16 = 0; k16 < 4; k16++) {
            const uint32_t ch = (uint32_t)(k16 * 2 + hb);
            uint32_t a0[4], a1[4];
            ldm4(a0, aP + rb0 + ((ch ^ rx0) << 4));
            ldm4(a1, aP + rb1 + ((ch ^ rx1) << 4));
            #pragma unroll
            for (int nt = 0; nt < 4; nt++) {
                const int fo = bbase + ((k16 * 16 + wn * 4 + nt) * 32 + lane) * 2;
                uint2 bv = *(const uint2*)&sm[fo];
                mma_fp16(acc[0][nt], a0, bv.x, bv.y);
                mma_fp16(acc[1][nt], a1, bv.x, bv.y);
            }
        }

        if (ks == 3) {
            // ---- epilogue for transform nc ----
            const uint8_t* binp = (const uint8_t*)&sm[OFF_BIN];
            const int b_r[4] = { binp[R0 * 8 + nc], binp[R1 * 8 + nc],
                                 binp[R2 * 8 + nc], binp[R3 * 8 + nc] };
            #pragma unroll
            for (int mt = 0; mt < 2; mt++) {
                const int Ra = mt ? R2 : R0;
                const int Rb = mt ? R3 : R1;
                const int ba = b_r[mt * 2 + 0], bb = b_r[mt * 2 + 1];
                #pragma unroll
                for (int nt = 0; nt < 4; nt++) {
                    const int seg = wn * 4 + nt;
                    const int n = nc * 128 + seg * 8 + 2 * l4;
                    const float2 b2v = *(const float2*)&sm[OFF_B2 + n];
                    float q0 = __expf(acc[mt][nt][0] + b2v.x);
                    float q1 = __expf(acc[mt][nt][1] + b2v.y);
                    float q2 = __expf(acc[mt][nt][2] + b2v.x);
                    float q3 = __expf(acc[mt][nt][3] + b2v.y);
                    float p0 = q0 + q1, p1 = q2 + q3;
                    // inclusive quad prefix
                    float ip0 = p0, ip1 = p1, u;
                    u = __shfl_up_sync(0xffffffffu, ip0, 1); if (l4 >= 1) ip0 += u;
                    u = __shfl_up_sync(0xffffffffu, ip0, 2); if (l4 >= 2) ip0 += u;
                    u = __shfl_up_sync(0xffffffffu, ip1, 1); if (l4 >= 1) ip1 += u;
                    u = __shfl_up_sync(0xffffffffu, ip1, 2); if (l4 >= 2) ip1 += u;
                    const float s0 = __shfl_sync(0xffffffffu, ip0, lane | 3);
                    const float s1 = __shfl_sync(0xffffffffu, ip1, lane | 3);
                    if (l4 == 0) {
                        sm[OFF_E + Ra * 20 + seg] = s0;
                        sm[OFF_E + Rb * 20 + seg] = s1;
                    }
                    if ((ba >> 3) == seg && l4 == ((ba & 7) >> 1)) {
                        sm[OFF_PRE + Ra] = (ip0 - p0) + ((ba & 1) ? q0 : 0.0f);
                        sm[OFF_QAT + Ra] = (ba & 1) ? q1 : q0;
                    }
                    if ((bb >> 3) == seg && l4 == ((bb & 7) >> 1)) {
                        sm[OFF_PRE + Rb] = (ip1 - p1) + ((bb & 1) ? q2 : 0.0f);
                        sm[OFF_QAT + Rb] = (bb & 1) ? q3 : q2;
                    }
                }
            }
            __syncthreads();

            if (tid < TILE_M) {
                const int row = tid;
                const int b = ((const uint8_t*)&sm[OFF_BIN])[row * 8 + nc];
                const int bs = b >> 3;
                float tot = 0.0f, pref = 0.0f;
                #pragma unroll
                for (int sg = 0; sg < 16; sg++) {
                    float v = sm[OFF_E + row * 20 + sg];
                    tot += v;
                    if (sg < bs) pref += v;
                }
                pref += sm[OFF_PRE + row];
                const float qat = sm[OFF_QAT + row];
                const float xb = __ldg(&x[(size_t)(g0 + row) * ROW_F + 8 + nc]);
                const float aa = xb * (float)NBINS;
                const float frac = aa - floorf(aa);
                const float inv = 1.0f / tot;
                out[(size_t)(g0 + row) * ROW_F + 8 + nc] = (qat * frac + pref) * inv;
                jac *= qat * (float)NBINS * inv;
            }
        }
    }

    // ---- jacobian + pass-through ----
    if (tid < TILE_M)
        out[(size_t)(g0 + tid) * ROW_F + 16] = jac;
    for (int i = tid; i < TILE_M * 8; i += NTHR) {
        int m = i >> 3, p = i & 7;
        out[(size_t)(g0 + m) * ROW_F + p] = __ldg(&x[(size_t)(g0 + m) * ROW_F + p]);
    }
}

extern "C" void kernel_launch(void* const* d_in, const int* in_sizes, int n_in,
                              void* d_out, int out_size) {
    const float* x  = (const float*)d_in[0];
    const float* W1 = (const float*)d_in[1];
    const float* b1 = (const float*)d_in[2];
    const float* W2 = (const float*)d_in[3];
    const float* b2 = (const float*)d_in[4];
    float* out = (float*)d_out;

    const int B = in_sizes[0] / ROW_F;          // 131072
    const int smem_bytes = SMEM_FLOATS * 4;     // 144 KB

    gplc_prep<<<256, 256>>>(W2);

    cudaFuncSetAttribute(gplc_main, cudaFuncAttributeMaxDynamicSharedMemorySize, smem_bytes);
    gplc_main<<<B / TILE_M, NTHR, smem_bytes>>>(x, W1, b1, b2, out);
}

// round 6
// speedup vs baseline: 5.0802x; 1.0412x over previous
#include <cuda_runtime.h>
#include <cuda_fp16.h>
#include <cstdint>

#define NBINS   128
#define HIDDEN  256
#define ROW_F   17
#define TILE_M  64
#define NTHR    256

// ---- smem float offsets ----
#define OFF_B2   0                  // 1024 f
#define OFF_BIN  1024               // u8[64][8] = 128 f
#define OFF_E    1152               // 2304 f: prologue W1T(2048)+b1(256); epilogue segsums[64][20]
#define OFF_QAT  3456               // 64 f
#define OFF_PRE  3520               // 64 f
#define OFF_A    3584               // byte 14336: A fp16, 4 panels x 8KB = 32KB
#define OFF_BST  11776              // byte 47104: 4 slots x 16KB = 64KB
#define SMEM_FLOATS (OFF_BST + 16384)   // 28160 f = 112640 B

// B fragments, mma.m16n8k16 B-operand order, fp16:
// [nc(8)][ks(4)][k16(4)][n8(16)][lane(32)] -> uint2{b0, b1}
__device__ uint2 g_bfrag[8 * 4 * 4 * 16 * 32];   // 512 KB

// ---------------- helpers ----------------
__device__ __forceinline__ uint32_t smem_u32(const void* p) {
    uint32_t a;
    asm("{ .reg .u64 t; cvta.to.shared.u64 t, %1; cvt.u32.u64 %0, t; }" : "=r"(a) : "l"(p));
    return a;
}
__device__ __forceinline__ uint32_t packh2(float lo, float hi) {
    __half2 t = __floats2half2_rn(lo, hi);   // x = lo (low 16 bits)
    return *(uint32_t*)&t;
}
__device__ __forceinline__ void ldm4(uint32_t* r, uint32_t addr) {
    asm volatile("ldmatrix.sync.aligned.m8n8.x4.shared.b16 {%0,%1,%2,%3}, [%4];"
        : "=r"(r[0]), "=r"(r[1]), "=r"(r[2]), "=r"(r[3]) : "r"(addr));
}
__device__ __forceinline__ void mma_fp16(float* d, const uint32_t* a, uint32_t b0, uint32_t b1) {
    asm volatile("mma.sync.aligned.m16n8k16.row.col.f32.f16.f16.f32 "
        "{%0,%1,%2,%3}, {%4,%5,%6,%7}, {%8,%9}, {%0,%1,%2,%3};"
        : "+f"(d[0]), "+f"(d[1]), "+f"(d[2]), "+f"(d[3])
        : "r"(a[0]), "r"(a[1]), "r"(a[2]), "r"(a[3]), "r"(b0), "r"(b1));
}
__device__ __forceinline__ void cp16(uint32_t sdst, const void* gsrc) {
    asm volatile("cp.async.cg.shared.global [%0], [%1], 16;" :: "r"(sdst), "l"(gsrc));
}
#define CP_COMMIT() asm volatile("cp.async.commit_group;")
#define CP_WAIT(n)  asm volatile("cp.async.wait_group %0;" :: "n"(n))

// ---------------- prep: W2 -> fp16 fragments ----------------
__global__ void gplc_prep(const float* __restrict__ W2) {
    const int idx  = blockIdx.x * 256 + threadIdx.x;       // 0..65535
    const int lane = idx & 31;
    const int n8   = (idx >> 5) & 15;
    const int k16  = (idx >> 9) & 3;
    const int ks   = (idx >> 11) & 3;
    const int nc   = idx >> 13;
    const int n  = nc * 128 + n8 * 8 + (lane >> 2);
    const int k0 = ks * 64 + k16 * 16 + 2 * (lane & 3);
    const float v0 = W2[(size_t)k0 * 1024 + n];
    const float v1 = W2[(size_t)(k0 + 1) * 1024 + n];
    const float v8 = W2[(size_t)(k0 + 8) * 1024 + n];
    const float v9 = W2[(size_t)(k0 + 9) * 1024 + n];
    g_bfrag[idx] = make_uint2(packh2(v0, v1), packh2(v8, v9));
}

// ---------------- main ----------------
__global__ __launch_bounds__(NTHR, 2)
void gplc_main(const float* __restrict__ x,
               const float* __restrict__ W1,
               const float* __restrict__ b1,
               const float* __restrict__ b2,
               float* __restrict__ out)
{
    extern __shared__ float sm[];
    const uint32_t smem_base = smem_u32(sm);
    const int tid  = threadIdx.x;
    const int w    = tid >> 5, lane = tid & 31;
    const int wm   = w >> 2, wn = w & 3;            // warp grid 2m x 4n
    const int m0   = wm * 32;                       // warp rows m0..m0+31
    const int l4   = lane & 3, lq = lane >> 2;
    const int g0   = blockIdx.x * TILE_M;

    // prefetch B stages 0..2 (3 groups)
    #pragma unroll
    for (int st = 0; st < 3; st++) {
        const char* src = (const char*)g_bfrag + (size_t)st * 16384;
        const uint32_t dst = smem_base + OFF_BST * 4 + st * 16384;
        #pragma unroll
        for (int j = 0; j < 4; j++) {
            int off = (tid + j * NTHR) * 16;
            cp16(dst + off, src + off);
        }
        CP_COMMIT();
    }

    // ---- prologue staging ----
    for (int i = tid; i < HIDDEN * 8; i += NTHR) {   // W1 transposed [k][8]
        int k = i >> 3, p = i & 7;
        sm[OFF_E + i] = W1[p * HIDDEN + k];
    }
    for (int i = tid; i < HIDDEN; i += NTHR) sm[OFF_E + 2048 + i] = b1[i];
    for (int i = tid; i < 1024; i += NTHR) sm[OFF_B2 + i] = b2[i];
    for (int i = tid; i < TILE_M * 8; i += NTHR) {   // bins u8
        int m = i >> 3, t = i & 7;
        float xb = __ldg(&x[(size_t)(g0 + m) * ROW_F + 8 + t]);
        int b = (int)floorf(xb * (float)NBINS);
        ((uint8_t*)&sm[OFF_BIN])[i] = (uint8_t)min(max(b, 0), NBINS - 1);
    }
    __syncthreads();

    // ---- first layer: h = relu(xA@W1+b1) -> fp16, swizzled A panels ----
    {
        const int m = tid & 63, quarter = tid >> 6;   // k in [quarter*64, +64)
        float xr[8];
        #pragma unroll
        for (int p = 0; p < 8; p++) xr[p] = __ldg(&x[(size_t)(g0 + m) * ROW_F + p]);
        const float4* W4 = (const float4*)&sm[OFF_E];
        char* Ap = (char*)sm + OFF_A * 4 + quarter * 8192;
        #pragma unroll
        for (int c = 0; c < 32; c++) {
            const int kin = 2 * c;
            const int k = quarter * 64 + kin;
            float4 wa = W4[k * 2], wb = W4[k * 2 + 1], wc = W4[k * 2 + 2], wd = W4[k * 2 + 3];
            float a0 = sm[OFF_E + 2048 + k], a1 = sm[OFF_E + 2048 + k + 1];
            a0 = fmaf(xr[0], wa.x, a0); a0 = fmaf(xr[1], wa.y, a0);
            a0 = fmaf(xr[2], wa.z, a0); a0 = fmaf(xr[3], wa.w, a0);
            a0 = fmaf(xr[4], wb.x, a0); a0 = fmaf(xr[5], wb.y, a0);
            a0 = fmaf(xr[6], wb.z, a0); a0 = fmaf(xr[7], wb.w, a0);
            a1 = fmaf(xr[0], wc.x, a1); a1 = fmaf(xr[1], wc.y, a1);
            a1 = fmaf(xr[2], wc.z, a1); a1 = fmaf(xr[3], wc.w, a1);
            a1 = fmaf(xr[4], wd.x, a1); a1 = fmaf(xr[5], wd.y, a1);
            a1 = fmaf(xr[6], wd.z, a1); a1 = fmaf(xr[7], wd.w, a1);
            a0 = fmaxf(a0, 0.0f); a1 = fmaxf(a1, 0.0f);
            const uint32_t off = (uint32_t)(m << 7)
                               + ((((uint32_t)(kin >> 3)) ^ (uint32_t)(m & 7)) << 4)
                               + (uint32_t)((kin & 7) << 1);
            *(uint32_t*)(Ap + off) = packh2(a0, a1);
        }
    }

    // per-lane A-row constants (ldmatrix addressing)
    const int lr = lane & 15, hb = lane >> 4;
    const int rowA0 = m0 + lr, rowA1 = m0 + 16 + lr;
    const uint32_t rb0 = (uint32_t)rowA0 << 7, rb1 = (uint32_t)rowA1 << 7;
    const uint32_t rx0 = rowA0 & 7, rx1 = rowA1 & 7;
    // epilogue row ids
    const int R0 = m0 + lq, R1 = m0 + lq + 8, R2 = m0 + 16 + lq, R3 = m0 + 24 + lq;

    float jac = (tid < TILE_M) ? __ldg(&x[(size_t)(g0 + tid) * ROW_F + 16]) : 0.0f;

    float acc[2][4][4];

    for (int s = 0; s < 32; s++) {
        const int nc = s >> 2, ks = s & 3;

        CP_WAIT(2);          // own cp groups: stage s complete
        __syncthreads();     // publish stage s; all warps done reading stage s-1

        if (s + 3 < 32) {    // refill slot (s+3)&3 == (s-1)&3
            const char* src = (const char*)g_bfrag + (size_t)(s + 3) * 16384;
            const uint32_t dst = smem_base + OFF_BST * 4 + ((s + 3) & 3) * 16384;
            #pragma unroll
            for (int j = 0; j < 4; j++) {
                int off = (tid + j * NTHR) * 16;
                cp16(dst + off, src + off);
            }
        }
        CP_COMMIT();

        if (ks == 0) {
            #pragma unroll
            for (int mt = 0; mt < 2; mt++)
                #pragma unroll
                for (int nt = 0; nt < 4; nt++)
                    #pragma unroll
                    for (int i = 0; i < 4; i++) acc[mt][nt][i] = 0.0f;
        }

        const uint32_t aP = smem_base + OFF_A * 4 + (uint32_t)ks * 8192;
        const int bbase = OFF_BST + (s & 3) * 4096;

        #pragma unroll
        for (int k16 = 0; k16 < 4; k16++) {
            const uint32_t ch = (uint32_t)(k16 * 2 + hb);
            uint32_t a0[4], a1[4];
            ldm4(a0, aP + rb0 + ((ch ^ rx0) << 4));
            ldm4(a1, aP + rb1 + ((ch ^ rx1) << 4));
            #pragma unroll
            for (int nt = 0; nt < 4; nt++) {
                const int fo = bbase + ((k16 * 16 + wn * 4 + nt) * 32 + lane) * 2;
                uint2 bv = *(const uint2*)&sm[fo];
                mma_fp16(acc[0][nt], a0, bv.x, bv.y);
                mma_fp16(acc[1][nt], a1, bv.x, bv.y);
            }
        }

        if (ks == 3) {
            // ---- epilogue for transform nc ----
            const uint8_t* binp = (const uint8_t*)&sm[OFF_BIN];
            const int b_r[4] = { binp[R0 * 8 + nc], binp[R1 * 8 + nc],
                                 binp[R2 * 8 + nc], binp[R3 * 8 + nc] };
            #pragma unroll
            for (int mt = 0; mt < 2; mt++) {
                const int Ra = mt ? R2 : R0;
                const int Rb = mt ? R3 : R1;
                const int ba = b_r[mt * 2 + 0], bb = b_r[mt * 2 + 1];
                #pragma unroll
                for (int nt = 0; nt < 4; nt++) {
                    const int seg = wn * 4 + nt;
                    const int n = nc * 128 + seg * 8 + 2 * l4;
                    const float2 b2v = *(const float2*)&sm[OFF_B2 + n];
                    float q0 = __expf(acc[mt][nt][0] + b2v.x);
                    float q1 = __expf(acc[mt][nt][1] + b2v.y);
                    float q2 = __expf(acc[mt][nt][2] + b2v.x);
                    float q3 = __expf(acc[mt][nt][3] + b2v.y);
                    float p0 = q0 + q1, p1 = q2 + q3;
                    // inclusive quad prefix
                    float ip0 = p0, ip1 = p1, u;
                    u = __shfl_up_sync(0xffffffffu, ip0, 1); if (l4 >= 1) ip0 += u;
                    u = __shfl_up_sync(0xffffffffu, ip0, 2); if (l4 >= 2) ip0 += u;
                    u = __shfl_up_sync(0xffffffffu, ip1, 1); if (l4 >= 1) ip1 += u;
                    u = __shfl_up_sync(0xffffffffu, ip1, 2); if (l4 >= 2) ip1 += u;
                    const float s0 = __shfl_sync(0xffffffffu, ip0, lane | 3);
                    const float s1 = __shfl_sync(0xffffffffu, ip1, lane | 3);
                    if (l4 == 0) {
                        sm[OFF_E + Ra * 20 + seg] = s0;
                        sm[OFF_E + Rb * 20 + seg] = s1;
                    }
                    if ((ba >> 3) == seg && l4 == ((ba & 7) >> 1)) {
                        sm[OFF_PRE + Ra] = (ip0 - p0) + ((ba & 1) ? q0 : 0.0f);
                        sm[OFF_QAT + Ra] = (ba & 1) ? q1 : q0;
                    }
                    if ((bb >> 3) == seg && l4 == ((bb & 7) >> 1)) {
                        sm[OFF_PRE + Rb] = (ip1 - p1) + ((bb & 1) ? q2 : 0.0f);
                        sm[OFF_QAT + Rb] = (bb & 1) ? q3 : q2;
                    }
                }
            }
            __syncthreads();

            if (tid < TILE_M) {
                const int row = tid;
                const int b = ((const uint8_t*)&sm[OFF_BIN])[row * 8 + nc];
                const int bs = b >> 3;
                float tot = 0.0f, pref = 0.0f;
                #pragma unroll
                for (int sg = 0; sg < 16; sg++) {
                    float v = sm[OFF_E + row * 20 + sg];
                    tot += v;
                    if (sg < bs) pref += v;
                }
                pref += sm[OFF_PRE + row];
                const float qat = sm[OFF_QAT + row];
                const float xb = __ldg(&x[(size_t)(g0 + row) * ROW_F + 8 + nc]);
                const float aa = xb * (float)NBINS;
                const float frac = aa - floorf(aa);
                const float inv = 1.0f / tot;
                out[(size_t)(g0 + row) * ROW_F + 8 + nc] = (qat * frac + pref) * inv;
                jac *= qat * (float)NBINS * inv;
            }
        }
    }

    // ---- jacobian + pass-through ----
    if (tid < TILE_M)
        out[(size_t)(g0 + tid) * ROW_F + 16] = jac;
    for (int i = tid; i < TILE_M * 8; i += NTHR) {
        int m = i >> 3, p = i & 7;
        out[(size_t)(g0 + m) * ROW_F + p] = __ldg(&x[(size_t)(g0 + m) * ROW_F + p]);
    }
}

extern "C" void kernel_launch(void* const* d_in, const int* in_sizes, int n_in,
                              void* d_out, int out_size) {
    const float* x  = (const float*)d_in[0];
    const float* W1 = (const float*)d_in[1];
    const float* b1 = (const float*)d_in[2];
    const float* W2 = (const float*)d_in[3];
    const float* b2 = (const float*)d_in[4];
    float* out = (float*)d_out;

    const int B = in_sizes[0] / ROW_F;          // 131072
    const int smem_bytes = SMEM_FLOATS * 4;     // 112640 B

    gplc_prep<<<256, 256>>>(W2);

    cudaFuncSetAttribute(gplc_main, cudaFuncAttributeMaxDynamicSharedMemorySize, smem_bytes);
    gplc_main<<<B / TILE_M, NTHR, smem_bytes>>>(x, W1, b1, b2, out);
}

// round 7
// speedup vs baseline: 6.2254x; 1.2254x over previous
#include <cuda_runtime.h>
#include <cuda_fp16.h>
#include <cstdint>

#define NBINS   128
#define HIDDEN  256
#define ROW_F   17
#define TILE_M  128
#define NTHR    256

// ---- smem float offsets ----
#define OFF_B2   0                  // 1024 f
#define OFF_BIN  1024               // u8[128][8] = 256 f
#define OFF_E    1280               // 2560 f: prologue W1T(2048)+b1(256); epilogue segsums[128][20]
#define OFF_QAT  3840               // 128 f
#define OFF_PRE  3968               // 128 f
#define OFF_A    4096               // byte 16384: A fp16, 4 panels x 16KB = 64KB
#define SMEM_FLOATS (OFF_A + 16384) // 20480 f = 80KB -> 2 CTAs/SM

// B fragments in LDG.128 form:
// [s(32)=nc*4+ks][k16(4)][wn(4)][pair(2)][lane(32)] -> uint4 {b0(nt0),b1(nt0),b0(nt1),b1(nt1)}
// nt = wn*4 + pair*2 + j ; col n = nc*128 + nt*8 + (lane>>2); k0 = ks*64 + k16*16 + 2*(lane&3)
__device__ uint4 g_bfrag[32 * 4 * 4 * 2 * 32];   // 32768 entries = 512 KB

// ---------------- helpers ----------------
__device__ __forceinline__ uint32_t smem_u32(const void* p) {
    uint32_t a;
    asm("{ .reg .u64 t; cvta.to.shared.u64 t, %1; cvt.u32.u64 %0, t; }" : "=r"(a) : "l"(p));
    return a;
}
__device__ __forceinline__ uint32_t packh2(float lo, float hi) {
    __half2 t = __floats2half2_rn(lo, hi);   // x = lo (low 16 bits)
    return *(uint32_t*)&t;
}
__device__ __forceinline__ void ldm4(uint32_t* r, uint32_t addr) {
    asm volatile("ldmatrix.sync.aligned.m8n8.x4.shared.b16 {%0,%1,%2,%3}, [%4];"
        : "=r"(r[0]), "=r"(r[1]), "=r"(r[2]), "=r"(r[3]) : "r"(addr));
}
__device__ __forceinline__ void mma_fp16(float* d, const uint32_t* a, uint32_t b0, uint32_t b1) {
    asm volatile("mma.sync.aligned.m16n8k16.row.col.f32.f16.f16.f32 "
        "{%0,%1,%2,%3}, {%4,%5,%6,%7}, {%8,%9}, {%0,%1,%2,%3};"
        : "+f"(d[0]), "+f"(d[1]), "+f"(d[2]), "+f"(d[3])
        : "r"(a[0]), "r"(a[1]), "r"(a[2]), "r"(a[3]), "r"(b0), "r"(b1));
}

// ---------------- prep: W2 -> fp16 fragments (LDG layout) ----------------
__global__ void gplc_prep(const float* __restrict__ W2) {
    const int idx  = blockIdx.x * 256 + threadIdx.x;       // 0..32767
    const int lane = idx & 31;
    const int pair = (idx >> 5) & 1;
    const int wn   = (idx >> 6) & 3;
    const int k16  = (idx >> 8) & 3;
    const int s    = idx >> 10;
    const int nc   = s >> 2, ks = s & 3;
    const int nt0  = wn * 4 + pair * 2;
    const int k0   = ks * 64 + k16 * 16 + 2 * (lane & 3);
    uint32_t r[4];
    #pragma unroll
    for (int j = 0; j < 2; j++) {
        const int n = nc * 128 + (nt0 + j) * 8 + (lane >> 2);
        const float v0 = W2[(size_t)k0 * 1024 + n];
        const float v1 = W2[(size_t)(k0 + 1) * 1024 + n];
        const float v8 = W2[(size_t)(k0 + 8) * 1024 + n];
        const float v9 = W2[(size_t)(k0 + 9) * 1024 + n];
        r[2 * j]     = packh2(v0, v1);
        r[2 * j + 1] = packh2(v8, v9);
    }
    g_bfrag[idx] = make_uint4(r[0], r[1], r[2], r[3]);
}

// ---------------- main ----------------
__global__ __launch_bounds__(NTHR, 2)
void gplc_main(const float* __restrict__ x,
               const float* __restrict__ W1,
               const float* __restrict__ b1,
               const float* __restrict__ b2,
               float* __restrict__ out)
{
    extern __shared__ float sm[];
    const uint32_t smem_base = smem_u32(sm);
    const int tid  = threadIdx.x;
    const int w    = tid >> 5, lane = tid & 31;
    const int wm   = w >> 2, wn = w & 3;            // warp grid 2m x 4n
    const int m0   = wm * 64;                       // warp rows m0..m0+63
    const int l4   = lane & 3, lq = lane >> 2;
    const int lr   = lane & 15, hb = lane >> 4;
    const int g0   = blockIdx.x * TILE_M;

    // ---- prologue staging ----
    for (int i = tid; i < HIDDEN * 8; i += NTHR) {   // W1 transposed [k][8]
        int k = i >> 3, p = i & 7;
        sm[OFF_E + i] = W1[p * HIDDEN + k];
    }
    for (int i = tid; i < HIDDEN; i += NTHR) sm[OFF_E + 2048 + i] = b1[i];
    for (int i = tid; i < 1024; i += NTHR) sm[OFF_B2 + i] = b2[i];
    for (int i = tid; i < TILE_M * 8; i += NTHR) {   // bins u8
        int m = i >> 3, t = i & 7;
        float xb = __ldg(&x[(size_t)(g0 + m) * ROW_F + 8 + t]);
        int b = (int)floorf(xb * (float)NBINS);
        ((uint8_t*)&sm[OFF_BIN])[i] = (uint8_t)min(max(b, 0), NBINS - 1);
    }
    __syncthreads();

    // ---- first layer: h = relu(xA@W1+b1) -> fp16, swizzled A panels ----
    {
        const int m = tid & 127, half = tid >> 7;    // k in [half*128, +128)
        float xr[8];
        #pragma unroll
        for (int p = 0; p < 8; p++) xr[p] = __ldg(&x[(size_t)(g0 + m) * ROW_F + p]);
        const float4* W4 = (const float4*)&sm[OFF_E];
        char* Ab = (char*)sm + OFF_A * 4;
        #pragma unroll
        for (int c = 0; c < 64; c++) {
            const int k = half * 128 + 2 * c;
            float4 wa = W4[k * 2], wb = W4[k * 2 + 1], wc = W4[k * 2 + 2], wd = W4[k * 2 + 3];
            float a0 = sm[OFF_E + 2048 + k], a1 = sm[OFF_E + 2048 + k + 1];
            a0 = fmaf(xr[0], wa.x, a0); a0 = fmaf(xr[1], wa.y, a0);
            a0 = fmaf(xr[2], wa.z, a0); a0 = fmaf(xr[3], wa.w, a0);
            a0 = fmaf(xr[4], wb.x, a0); a0 = fmaf(xr[5], wb.y, a0);
            a0 = fmaf(xr[6], wb.z, a0); a0 = fmaf(xr[7], wb.w, a0);
            a1 = fmaf(xr[0], wc.x, a1); a1 = fmaf(xr[1], wc.y, a1);
            a1 = fmaf(xr[2], wc.z, a1); a1 = fmaf(xr[3], wc.w, a1);
            a1 = fmaf(xr[4], wd.x, a1); a1 = fmaf(xr[5], wd.y, a1);
            a1 = fmaf(xr[6], wd.z, a1); a1 = fmaf(xr[7], wd.w, a1);
            a0 = fmaxf(a0, 0.0f); a1 = fmaxf(a1, 0.0f);
            const int panel = k >> 6, kin = k & 63;
            const uint32_t off = (uint32_t)panel * 16384 + (uint32_t)(m << 7)
                               + ((((uint32_t)(kin >> 3)) ^ (uint32_t)(m & 7)) << 4)
                               + (uint32_t)((kin & 7) << 1);
            *(uint32_t*)(Ab + off) = packh2(a0, a1);
        }
    }
    __syncthreads();   // A panels visible to all warps

    float jac = (tid < TILE_M) ? __ldg(&x[(size_t)(g0 + tid) * ROW_F + 16]) : 0.0f;

    float acc[4][4][4];

    for (int s = 0; s < 32; s++) {
        const int nc = s >> 2, ks = s & 3;

        if (ks == 0) {
            #pragma unroll
            for (int mt = 0; mt < 4; mt++)
                #pragma unroll
                for (int nt = 0; nt < 4; nt++)
                    #pragma unroll
                    for (int i = 0; i < 4; i++) acc[mt][nt][i] = 0.0f;
        }

        const uint32_t aP = smem_base + OFF_A * 4 + (uint32_t)ks * 16384;
        const uint4* bp = g_bfrag + (((size_t)s * 4) * 4 + wn) * 2 * 32 + lane;

        #pragma unroll
        for (int k16 = 0; k16 < 4; k16++) {
            // B fragments straight from L2 (coalesced LDG.128, no smem round-trip)
            const uint4 bva = __ldg(bp + (k16 * 4) * 2 * 32);
            const uint4 bvb = __ldg(bp + ((k16 * 4) * 2 + 1) * 32);
            const uint32_t ch = (uint32_t)(k16 * 2 + hb);
            uint32_t a[4][4];
            #pragma unroll
            for (int mt = 0; mt < 4; mt++) {
                const int row = m0 + mt * 16 + lr;
                ldm4(a[mt], aP + ((uint32_t)row << 7) + ((ch ^ (uint32_t)(row & 7)) << 4));
            }
            #pragma unroll
            for (int mt = 0; mt < 4; mt++) {
                mma_fp16(acc[mt][0], a[mt], bva.x, bva.y);
                mma_fp16(acc[mt][1], a[mt], bva.z, bva.w);
                mma_fp16(acc[mt][2], a[mt], bvb.x, bvb.y);
                mma_fp16(acc[mt][3], a[mt], bvb.z, bvb.w);
            }
        }

        if (ks == 3) {
            // ---- epilogue for transform nc ----
            const uint8_t* binp = (const uint8_t*)&sm[OFF_BIN];
            #pragma unroll
            for (int mt = 0; mt < 4; mt++) {
                const int Ra = m0 + mt * 16 + lq;
                const int Rb = Ra + 8;
                const int ba = binp[Ra * 8 + nc], bb = binp[Rb * 8 + nc];
                #pragma unroll
                for (int nt = 0; nt < 4; nt++) {
                    const int seg = wn * 4 + nt;
                    const int n = nc * 128 + seg * 8 + 2 * l4;
                    const float2 b2v = *(const float2*)&sm[OFF_B2 + n];
                    float q0 = __expf(acc[mt][nt][0] + b2v.x);
                    float q1 = __expf(acc[mt][nt][1] + b2v.y);
                    float q2 = __expf(acc[mt][nt][2] + b2v.x);
                    float q3 = __expf(acc[mt][nt][3] + b2v.y);
                    float p0 = q0 + q1, p1 = q2 + q3;
                    // inclusive quad prefix
                    float ip0 = p0, ip1 = p1, u;
                    u = __shfl_up_sync(0xffffffffu, ip0, 1); if (l4 >= 1) ip0 += u;
                    u = __shfl_up_sync(0xffffffffu, ip0, 2); if (l4 >= 2) ip0 += u;
                    u = __shfl_up_sync(0xffffffffu, ip1, 1); if (l4 >= 1) ip1 += u;
                    u = __shfl_up_sync(0xffffffffu, ip1, 2); if (l4 >= 2) ip1 += u;
                    const float s0 = __shfl_sync(0xffffffffu, ip0, lane | 3);
                    const float s1 = __shfl_sync(0xffffffffu, ip1, lane | 3);
                    if (l4 == 0) {
                        sm[OFF_E + Ra * 20 + seg] = s0;
                        sm[OFF_E + Rb * 20 + seg] = s1;
                    }
                    if ((ba >> 3) == seg && l4 == ((ba & 7) >> 1)) {
                        sm[OFF_PRE + Ra] = (ip0 - p0) + ((ba & 1) ? q0 : 0.0f);
                        sm[OFF_QAT + Ra] = (ba & 1) ? q1 : q0;
                    }
                    if ((bb >> 3) == seg && l4 == ((bb & 7) >> 1)) {
                        sm[OFF_PRE + Rb] = (ip1 - p1) + ((bb & 1) ? q2 : 0.0f);
                        sm[OFF_QAT + Rb] = (bb & 1) ? q3 : q2;
                    }
                }
            }
            __syncthreads();   // segsums/pre/qat published

            if (tid < TILE_M) {
                const int row = tid;
                const int b = ((const uint8_t*)&sm[OFF_BIN])[row * 8 + nc];
                const int bs = b >> 3;
                float tot = 0.0f, pref = 0.0f;
                #pragma unroll
                for (int sg = 0; sg < 16; sg++) {
                    float v = sm[OFF_E + row * 20 + sg];
                    tot += v;
                    if (sg < bs) pref += v;
                }
                pref += sm[OFF_PRE + row];
                const float qat = sm[OFF_QAT + row];
                const float xb = __ldg(&x[(size_t)(g0 + row) * ROW_F + 8 + nc]);
                const float aa = xb * (float)NBINS;
                const float frac = aa - floorf(aa);
                const float inv = 1.0f / tot;
                out[(size_t)(g0 + row) * ROW_F + 8 + nc] = (qat * frac + pref) * inv;
                jac *= qat * (float)NBINS * inv;
            }
            __syncthreads();   // finisher done before next nc reuses OFF_E
        }
    }

    // ---- jacobian + pass-through ----
    if (tid < TILE_M)
        out[(size_t)(g0 + tid) * ROW_F + 16] = jac;
    for (int i = tid; i < TILE_M * 8; i += NTHR) {
        int m = i >> 3, p = i & 7;
        out[(size_t)(g0 + m) * ROW_F + p] = __ldg(&x[(size_t)(g0 + m) * ROW_F + p]);
    }
}

extern "C" void kernel_launch(void* const* d_in, const int* in_sizes, int n_in,
                              void* d_out, int out_size) {
    const float* x  = (const float*)d_in[0];
    const float* W1 = (const float*)d_in[1];
    const float* b1 = (const float*)d_in[2];
    const float* W2 = (const float*)d_in[3];
    const float* b2 = (const float*)d_in[4];
    float* out = (float*)d_out;

    const int B = in_sizes[0] / ROW_F;          // 131072
    const int smem_bytes = SMEM_FLOATS * 4;     // 80 KB

    gplc_prep<<<128, 256>>>(W2);

    cudaFuncSetAttribute(gplc_main, cudaFuncAttributeMaxDynamicSharedMemorySize, smem_bytes);
    gplc_main<<<B / TILE_M, NTHR, smem_bytes>>>(x, W1, b1, b2, out);
}